// round 1
// baseline (speedup 1.0000x reference)
#include <cuda_runtime.h>
#include <cstdint>

// Problem constants (fixed by the dataset)
#define BH    32        // B*H = 4*8
#define M_DIM 2048
#define K_DIM 2048
#define N_DIM 64

// out has BH*M_DIM*N_DIM = 4,194,304 floats

__global__ void zero_out_kernel(float4* out, int n4) {
    int i = blockIdx.x * blockDim.x + threadIdx.x;
    if (i < n4) out[i] = make_float4(0.f, 0.f, 0.f, 0.f);
}

// 16 threads per nonzero; each thread covers 4 of the 64 output columns.
__global__ void spmm_scatter_kernel(const float* __restrict__ values,
                                    const float* __restrict__ bmat,
                                    const int*   __restrict__ idx_bh,
                                    const int*   __restrict__ idx_m,
                                    const int*   __restrict__ idx_k,
                                    float* __restrict__ out,
                                    int nnz) {
    long long t = (long long)blockIdx.x * blockDim.x + threadIdx.x;
    int nz  = (int)(t >> 4);
    if (nz >= nnz) return;
    int sub = (int)(t & 15);          // 0..15 -> columns [sub*4, sub*4+4)

    float v  = __ldg(&values[nz]);
    int   bh = __ldg(&idx_bh[nz]);
    int   m  = __ldg(&idx_m[nz]);
    int   k  = __ldg(&idx_k[nz]);

    const float4* brow = reinterpret_cast<const float4*>(
        bmat + ((size_t)bh * K_DIM + (size_t)k) * N_DIM) + sub;
    float4 bv = __ldg(brow);

    float4 r;
    r.x = v * bv.x; r.y = v * bv.y; r.z = v * bv.z; r.w = v * bv.w;

    float* dst = out + ((size_t)bh * M_DIM + (size_t)m) * N_DIM + sub * 4;
    // Vector fp32 reduction at L2, no return value (REDG, not ATOMG).
    asm volatile("red.global.add.v4.f32 [%0], {%1, %2, %3, %4};"
                 :: "l"(dst), "f"(r.x), "f"(r.y), "f"(r.z), "f"(r.w)
                 : "memory");
}

extern "C" void kernel_launch(void* const* d_in, const int* in_sizes, int n_in,
                              void* d_out, int out_size) {
    const float* values = (const float*)d_in[0];
    const float* bmat   = (const float*)d_in[1];
    const int*   idx_bh = (const int*)d_in[2];
    const int*   idx_m  = (const int*)d_in[3];
    const int*   idx_k  = (const int*)d_in[4];
    float*       out    = (float*)d_out;

    int nnz = in_sizes[0];

    // 1) zero the (poisoned) output
    int n4 = out_size / 4;                       // float4 count
    {
        int threads = 256;
        int blocks  = (n4 + threads - 1) / threads;
        zero_out_kernel<<<blocks, threads>>>((float4*)out, n4);
    }

    // 2) scatter-accumulate: 16 threads per nonzero
    {
        long long total = (long long)nnz * 16;
        int threads = 256;
        long long blocks = (total + threads - 1) / threads;
        spmm_scatter_kernel<<<(int)blocks, threads>>>(values, bmat, idx_bh,
                                                      idx_m, idx_k, out, nnz);
    }
}

// round 2
// speedup vs baseline: 1.9897x; 1.9897x over previous
#include <cuda_runtime.h>
#include <cstdint>

// Problem constants (fixed by the dataset)
#define BH     32        // B*H = 4*8
#define M_DIM  2048
#define K_DIM  2048
#define N_DIM  64
#define NSEG   (BH * M_DIM)   // 65536 output rows/segments
#define CAP    160            // per-segment bin capacity (Poisson(64): P(overflow) ~ 1e-17)

// Scratch: per-segment cursor + fixed-capacity bins of packed (k, value) pairs.
__device__ unsigned int       g_count[NSEG];
__device__ unsigned long long g_slots[(size_t)NSEG * CAP];   // 80 MB

__global__ void zero_counts_kernel() {
    int i = blockIdx.x * blockDim.x + threadIdx.x;
    if (i < NSEG) g_count[i] = 0u;
}

// One thread per nonzero: append (k, v) to its segment's bin.
__global__ void bin_kernel(const float* __restrict__ values,
                           const int*   __restrict__ idx_bh,
                           const int*   __restrict__ idx_m,
                           const int*   __restrict__ idx_k,
                           int nnz) {
    int i = blockIdx.x * blockDim.x + threadIdx.x;
    if (i >= nnz) return;

    float v  = values[i];
    int   bh = idx_bh[i];
    int   m  = idx_m[i];
    int   k  = idx_k[i];

    int seg = bh * M_DIM + m;
    unsigned pos = atomicAdd(&g_count[seg], 1u);
    if (pos < CAP) {
        unsigned long long p =
            ((unsigned long long)(unsigned)k << 32) |
            (unsigned long long)__float_as_uint(v);
        g_slots[(size_t)seg * CAP + pos] = p;
    }
}

// One half-warp (16 lanes) per segment. Each lane owns 4 output columns
// (float4) in registers; gather b rows from L2; single STG.128 at the end.
__global__ void reduce_kernel(const float* __restrict__ bmat,
                              float*       __restrict__ out) {
    int gwarp = (blockIdx.x * blockDim.x + threadIdx.x) >> 5;
    int lane  = threadIdx.x & 31;
    int half  = lane >> 4;          // 0 or 1: which segment of this warp
    int hl    = lane & 15;          // lane within half-warp -> column group

    int seg = gwarp * 2 + half;
    if (seg >= NSEG) return;

    int cnt = (int)min(g_count[seg], (unsigned)CAP);
    int bh  = seg >> 11;            // seg / M_DIM

    // b row base for this bh, offset to this lane's float4 column group
    const float4* bb = reinterpret_cast<const float4*>(
                           bmat + (size_t)bh * K_DIM * N_DIM) + hl;
    const unsigned long long* sl = g_slots + (size_t)seg * CAP;

    float4 acc = make_float4(0.f, 0.f, 0.f, 0.f);

    int j = 0;
    // Unroll by 4: 4 independent gathers in flight to hide L2 latency.
    for (; j + 4 <= cnt; j += 4) {
        // 32B of metadata, aligned (CAP*8 and j*8 are 32B-aligned)
        ulonglong2 q0 = *reinterpret_cast<const ulonglong2*>(sl + j);
        ulonglong2 q1 = *reinterpret_cast<const ulonglong2*>(sl + j + 2);

        int   k0 = (int)(q0.x >> 32);  float v0 = __uint_as_float((unsigned)q0.x);
        int   k1 = (int)(q0.y >> 32);  float v1 = __uint_as_float((unsigned)q0.y);
        int   k2 = (int)(q1.x >> 32);  float v2 = __uint_as_float((unsigned)q1.x);
        int   k3 = (int)(q1.y >> 32);  float v3 = __uint_as_float((unsigned)q1.y);

        float4 b0 = __ldg(bb + ((size_t)k0 << 4));
        float4 b1 = __ldg(bb + ((size_t)k1 << 4));
        float4 b2 = __ldg(bb + ((size_t)k2 << 4));
        float4 b3 = __ldg(bb + ((size_t)k3 << 4));

        acc.x += v0 * b0.x; acc.y += v0 * b0.y; acc.z += v0 * b0.z; acc.w += v0 * b0.w;
        acc.x += v1 * b1.x; acc.y += v1 * b1.y; acc.z += v1 * b1.z; acc.w += v1 * b1.w;
        acc.x += v2 * b2.x; acc.y += v2 * b2.y; acc.z += v2 * b2.z; acc.w += v2 * b2.w;
        acc.x += v3 * b3.x; acc.y += v3 * b3.y; acc.z += v3 * b3.z; acc.w += v3 * b3.w;
    }
    for (; j < cnt; j++) {
        unsigned long long p = sl[j];
        int   k = (int)(p >> 32);
        float v = __uint_as_float((unsigned)p);
        float4 bv = __ldg(bb + ((size_t)k << 4));
        acc.x += v * bv.x; acc.y += v * bv.y; acc.z += v * bv.z; acc.w += v * bv.w;
    }

    // One plain store per lane; covers every output element (empty segs -> 0).
    float4* dst = reinterpret_cast<float4*>(out + (size_t)seg * N_DIM) + hl;
    *dst = acc;
}

extern "C" void kernel_launch(void* const* d_in, const int* in_sizes, int n_in,
                              void* d_out, int out_size) {
    const float* values = (const float*)d_in[0];
    const float* bmat   = (const float*)d_in[1];
    const int*   idx_bh = (const int*)d_in[2];
    const int*   idx_m  = (const int*)d_in[3];
    const int*   idx_k  = (const int*)d_in[4];
    float*       out    = (float*)d_out;

    int nnz = in_sizes[0];

    // 1) reset per-segment cursors
    zero_counts_kernel<<<(NSEG + 255) / 256, 256>>>();

    // 2) bin nonzeros by output segment
    bin_kernel<<<(nnz + 255) / 256, 256>>>(values, idx_bh, idx_m, idx_k, nnz);

    // 3) register-accumulated segmented reduction; plain stores, no atomics
    {
        int warps_needed  = (NSEG + 1) / 2;     // 2 segments per warp
        int threads       = 256;                // 8 warps -> 16 segments per block
        int blocks        = (warps_needed * 32 + threads - 1) / threads;
        reduce_kernel<<<blocks, threads>>>(bmat, out);
    }
}